// round 5
// baseline (speedup 1.0000x reference)
#include <cuda_runtime.h>
#include <cuda_bf16.h>
#include <cstdint>

#define B_   8
#define N_   2048
#define DIN  256
#define HID  64
#define TI   64
#define CH   32
#define NCH  (N_ / CH)
#define L2E  1.4426950408889634f

// Scratch (device globals — no allocation allowed)
__device__ float    g_Wh[B_ * N_ * HID];            // fp32 row-major (for compute_f)
__device__ uint32_t g_Whh[B_ * N_ * HID / 2];       // bf16x2 hi  [node][h/2]
__device__ uint32_t g_Whl[B_ * N_ * HID / 2];       // bf16x2 lo
__device__ float g_f1e[B_ * N_], g_f1s[B_ * N_];    // f1*log2e, 0.2*f1*log2e
__device__ float g_f2e[B_ * N_], g_f2s[B_ * N_];

// ---------------- helpers ----------------
static __device__ __forceinline__ uint32_t smem_u32(const void* p) {
    uint32_t a;
    asm("{ .reg .u64 t; cvta.to.shared.u64 t, %1; cvt.u32.u64 %0, t; }"
        : "=r"(a) : "l"(p));
    return a;
}
static __device__ __forceinline__ float ex2(float x) {
    float y;
    asm("ex2.approx.f32 %0, %1;" : "=f"(y) : "f"(x));
    return y;
}
// pack two fp32 -> bf16x2 (w0 -> low half, w1 -> high half)
static __device__ __forceinline__ uint32_t pack2(float w0, float w1) {
    uint32_t r;
    asm("cvt.rn.bf16x2.f32 %0, %1, %2;" : "=r"(r) : "f"(w1), "f"(w0));
    return r;
}
// split pair into bf16 hi + bf16 lo (exact residual)
static __device__ __forceinline__ void split2(float w0, float w1,
                                              uint32_t& hi, uint32_t& lo) {
    uint32_t h = pack2(w0, w1);
    float h0 = __uint_as_float(h << 16);
    float h1 = __uint_as_float(h & 0xFFFF0000u);
    lo = pack2(w0 - h0, w1 - h1);
    hi = h;
}
static __device__ __forceinline__ void ldsm4t(uint32_t& r0, uint32_t& r1,
                                              uint32_t& r2, uint32_t& r3,
                                              const void* p) {
    uint32_t a = smem_u32(p);
    asm volatile("ldmatrix.sync.aligned.m8n8.x4.trans.shared.b16 {%0,%1,%2,%3}, [%4];"
                 : "=r"(r0), "=r"(r1), "=r"(r2), "=r"(r3) : "r"(a));
}
static __device__ __forceinline__ void mma16816(float* c, const uint32_t* a,
                                                uint32_t b0, uint32_t b1) {
    asm volatile(
        "mma.sync.aligned.m16n8k16.row.col.f32.bf16.bf16.f32 "
        "{%0,%1,%2,%3}, {%4,%5,%6,%7}, {%8,%9}, {%0,%1,%2,%3};"
        : "+f"(c[0]), "+f"(c[1]), "+f"(c[2]), "+f"(c[3])
        : "r"(a[0]), "r"(a[1]), "r"(a[2]), "r"(a[3]), "r"(b0), "r"(b1));
}

// ---------------------------------------------------------------------------
// Kernel A: Wh = X @ W ; emits fp32 Wh + bf16 hi/lo packed copies.
// ---------------------------------------------------------------------------
__global__ __launch_bounds__(256) void gemm_wh(const float* __restrict__ X,
                                               const float* __restrict__ W) {
    __shared__ __align__(16) float Xs[2][64][36];
    __shared__ __align__(16) float Ws[2][32][64];

    const int tid = threadIdx.x;
    const int tx = tid & 15;
    const int ty = tid >> 4;
    const int r0 = blockIdx.x * 64;
    const int xr = tid >> 3, xk = (tid & 7) << 2;
    const int wk = tid >> 4, wh_ = (tid & 15) << 2;

    float acc[4][4];
#pragma unroll
    for (int i = 0; i < 4; i++)
#pragma unroll
        for (int j = 0; j < 4; j++) acc[i][j] = 0.f;

    float4 xv0, xv1, wv0, wv1;
    xv0 = *(const float4*)(X + (size_t)(r0 + xr) * DIN + xk);
    xv1 = *(const float4*)(X + (size_t)(r0 + 32 + xr) * DIN + xk);
    wv0 = *(const float4*)(W + (size_t)wk * HID + wh_);
    wv1 = *(const float4*)(W + (size_t)(16 + wk) * HID + wh_);
    *(float4*)&Xs[0][xr][xk]      = xv0;
    *(float4*)&Xs[0][32 + xr][xk] = xv1;
    *(float4*)&Ws[0][wk][wh_]      = wv0;
    *(float4*)&Ws[0][16 + wk][wh_] = wv1;
    __syncthreads();

    for (int kt = 0; kt < 8; kt++) {
        const int cur = kt & 1, nxt = cur ^ 1;
        if (kt < 7) {
            const int k0 = (kt + 1) * 32;
            xv0 = *(const float4*)(X + (size_t)(r0 + xr) * DIN + k0 + xk);
            xv1 = *(const float4*)(X + (size_t)(r0 + 32 + xr) * DIN + k0 + xk);
            wv0 = *(const float4*)(W + (size_t)(k0 + wk) * HID + wh_);
            wv1 = *(const float4*)(W + (size_t)(k0 + 16 + wk) * HID + wh_);
        }
#pragma unroll
        for (int k = 0; k < 32; k++) {
            float4 wv = *(float4*)&Ws[cur][k][tx << 2];
#pragma unroll
            for (int rr = 0; rr < 4; rr++) {
                float xv = Xs[cur][(ty << 2) + rr][k];
                acc[rr][0] += xv * wv.x;
                acc[rr][1] += xv * wv.y;
                acc[rr][2] += xv * wv.z;
                acc[rr][3] += xv * wv.w;
            }
        }
        if (kt < 7) {
            *(float4*)&Xs[nxt][xr][xk]      = xv0;
            *(float4*)&Xs[nxt][32 + xr][xk] = xv1;
            *(float4*)&Ws[nxt][wk][wh_]      = wv0;
            *(float4*)&Ws[nxt][16 + wk][wh_] = wv1;
        }
        __syncthreads();
    }

#pragma unroll
    for (int rr = 0; rr < 4; rr++) {
        const int node = r0 + (ty << 2) + rr;
        float4 v = make_float4(acc[rr][0], acc[rr][1], acc[rr][2], acc[rr][3]);
        *(float4*)&g_Wh[(size_t)node * HID + (tx << 2)] = v;
        uint32_t h01, l01, h23, l23;
        split2(v.x, v.y, h01, l01);
        split2(v.z, v.w, h23, l23);
        size_t o = (size_t)node * 32 + tx * 2;
        *(uint2*)&g_Whh[o] = make_uint2(h01, h23);
        *(uint2*)&g_Whl[o] = make_uint2(l01, l23);
    }
}

// ---------------------------------------------------------------------------
// Kernel B: f1/f2 per node, pre-scaled by log2e (and 0.2*log2e).
// ---------------------------------------------------------------------------
__global__ __launch_bounds__(256) void compute_f(const float* __restrict__ a) {
    const int row = blockIdx.x * 8 + (threadIdx.x >> 5);
    const int lane = threadIdx.x & 31;
    const float* wh = g_Wh + (size_t)row * HID;
    float w0 = wh[lane], w1 = wh[lane + 32];
    float f1 = w0 * a[lane] + w1 * a[lane + 32];
    float f2 = w0 * a[HID + lane] + w1 * a[HID + lane + 32];
#pragma unroll
    for (int s = 16; s > 0; s >>= 1) {
        f1 += __shfl_xor_sync(0xffffffffu, f1, s);
        f2 += __shfl_xor_sync(0xffffffffu, f2, s);
    }
    if (lane == 0) {
        g_f1e[row] = f1 * L2E;
        g_f1s[row] = 0.2f * f1 * L2E;
        g_f2e[row] = f2 * L2E;
        g_f2s[row] = 0.2f * f2 * L2E;
    }
}

// ---------------------------------------------------------------------------
// Main kernel: masked-softmax attention * Wh via mma.sync bf16 (2-term split).
// TI=64, 128 threads (4 warps), grid = 256 blocks -> ~2 CTAs/SM: two
// independent barrier domains per SM hide shfl/ex2/LDSM/HMMA latency.
// Warp w owns rows w*16..w*16+15; A fragments computed in mma register
// layout (never touch SMEM); B (Wh bf16 hi/lo) double-buffered in SMEM with
// 144B-padded rows -> conflict-free ldmatrix.x4.trans. One barrier per chunk.
// ---------------------------------------------------------------------------
__global__ __launch_bounds__(128) void gat_main(const int* __restrict__ adj,
                                                float* __restrict__ out) {
    __shared__ __align__(16) __nv_bfloat16 Bs[2][2][CH][72];  // [buf][split][k][n]

    const int tid = threadIdx.x;
    const int lane = tid & 31, wid = tid >> 5;   // wid 0..3
    const int g = lane >> 2, tg = lane & 3;
    const int b = blockIdx.x >> 5;
    const int i0 = (blockIdx.x & 31) * TI;
    const int base = b * N_;

    const int r_lo = wid * 16 + g, r_hi = r_lo + 8;

    // B staging: 2 uint4 per thread per split; slot p -> node p>>3, h (p&7)*8
    const int fj0 = tid >> 3, fh0 = (tid & 7) * 8;
    const int fj1 = (tid + 128) >> 3, fh1 = (tid & 7) * 8;  // second slot
    const uint32_t* whh = g_Whh + (size_t)base * 32;
    const uint32_t* whl = g_Whl + (size_t)base * 32;

    const float f1e_lo = g_f1e[base + i0 + r_lo], f1s_lo = g_f1s[base + i0 + r_lo];
    const float f1e_hi = g_f1e[base + i0 + r_hi], f1s_hi = g_f1s[base + i0 + r_hi];
    float dlo = 0.f, dhi = 0.f;

    float c[8][4];
#pragma unroll
    for (int nt = 0; nt < 8; nt++)
#pragma unroll
        for (int q = 0; q < 4; q++) c[nt][q] = 0.f;

    const int* adjlo = adj + (size_t)b * N_ * N_ + (size_t)(i0 + r_lo) * N_;
    const int* adjhi = adjlo + (size_t)8 * N_;

    // ---- prefetch chunk 0 ----
    int2 av[8];
#pragma unroll
    for (int s = 0; s < 2; s++) {
        av[s * 4 + 0] = *(const int2*)&adjlo[s * 16 + 2 * tg];
        av[s * 4 + 1] = *(const int2*)&adjlo[s * 16 + 2 * tg + 8];
        av[s * 4 + 2] = *(const int2*)&adjhi[s * 16 + 2 * tg];
        av[s * 4 + 3] = *(const int2*)&adjhi[s * 16 + 2 * tg + 8];
    }
    float f2e_c = g_f2e[base + lane];
    float f2s_c = g_f2s[base + lane];
    uint4 bhv0 = *(const uint4*)&whh[(size_t)fj0 * 32 + (fh0 >> 1)];
    uint4 bhv1 = *(const uint4*)&whh[(size_t)fj1 * 32 + (fh1 >> 1)];
    uint4 blv0 = *(const uint4*)&whl[(size_t)fj0 * 32 + (fh0 >> 1)];
    uint4 blv1 = *(const uint4*)&whl[(size_t)fj1 * 32 + (fh1 >> 1)];

#pragma unroll 2
    for (int t = 0; t < NCH; t++) {
        const int buf = t & 1;

        // store B(t) into SMEM buffer
        *(uint4*)&Bs[buf][0][fj0][fh0] = bhv0;
        *(uint4*)&Bs[buf][0][fj1][fh1] = bhv1;
        *(uint4*)&Bs[buf][1][fj0][fh0] = blv0;
        *(uint4*)&Bs[buf][1][fj1][fh1] = blv1;

        // issue prefetch for t+1 (latency hides under stage1 + mma)
        const int tn = (t + 1 < NCH) ? t + 1 : t;
        const int j0n = tn * CH;
        int2 nav[8];
#pragma unroll
        for (int s = 0; s < 2; s++) {
            nav[s * 4 + 0] = *(const int2*)&adjlo[j0n + s * 16 + 2 * tg];
            nav[s * 4 + 1] = *(const int2*)&adjlo[j0n + s * 16 + 2 * tg + 8];
            nav[s * 4 + 2] = *(const int2*)&adjhi[j0n + s * 16 + 2 * tg];
            nav[s * 4 + 3] = *(const int2*)&adjhi[j0n + s * 16 + 2 * tg + 8];
        }
        float nf2e = g_f2e[base + j0n + lane];
        float nf2s = g_f2s[base + j0n + lane];
        uint4 nbh0 = *(const uint4*)&whh[(size_t)(j0n + fj0) * 32 + (fh0 >> 1)];
        uint4 nbh1 = *(const uint4*)&whh[(size_t)(j0n + fj1) * 32 + (fh1 >> 1)];
        uint4 nbl0 = *(const uint4*)&whl[(size_t)(j0n + fj0) * 32 + (fh0 >> 1)];
        uint4 nbl1 = *(const uint4*)&whl[(size_t)(j0n + fj1) * 32 + (fh1 >> 1)];

        // stage1: attention-weight A-fragments (hi/lo) in mma layout
        uint32_t ah[2][4], al[2][4];
#pragma unroll
        for (int s = 0; s < 2; s++) {
            const int jb = s * 16 + 2 * tg;
            float e0 = __shfl_sync(0xffffffffu, f2e_c, jb);
            float e1 = __shfl_sync(0xffffffffu, f2e_c, jb + 1);
            float e8 = __shfl_sync(0xffffffffu, f2e_c, jb + 8);
            float e9 = __shfl_sync(0xffffffffu, f2e_c, jb + 9);
            float s0 = __shfl_sync(0xffffffffu, f2s_c, jb);
            float s1 = __shfl_sync(0xffffffffu, f2s_c, jb + 1);
            float s8 = __shfl_sync(0xffffffffu, f2s_c, jb + 8);
            float s9 = __shfl_sync(0xffffffffu, f2s_c, jb + 9);

            float wl0 = (av[s * 4 + 0].x > 0) ? ex2(fmaxf(f1e_lo + e0, f1s_lo + s0)) : 0.f;
            float wl1 = (av[s * 4 + 0].y > 0) ? ex2(fmaxf(f1e_lo + e1, f1s_lo + s1)) : 0.f;
            float wl8 = (av[s * 4 + 1].x > 0) ? ex2(fmaxf(f1e_lo + e8, f1s_lo + s8)) : 0.f;
            float wl9 = (av[s * 4 + 1].y > 0) ? ex2(fmaxf(f1e_lo + e9, f1s_lo + s9)) : 0.f;
            float wh0 = (av[s * 4 + 2].x > 0) ? ex2(fmaxf(f1e_hi + e0, f1s_hi + s0)) : 0.f;
            float wh1 = (av[s * 4 + 2].y > 0) ? ex2(fmaxf(f1e_hi + e1, f1s_hi + s1)) : 0.f;
            float wh8 = (av[s * 4 + 3].x > 0) ? ex2(fmaxf(f1e_hi + e8, f1s_hi + s8)) : 0.f;
            float wh9 = (av[s * 4 + 3].y > 0) ? ex2(fmaxf(f1e_hi + e9, f1s_hi + s9)) : 0.f;

            dlo += (wl0 + wl1) + (wl8 + wl9);
            dhi += (wh0 + wh1) + (wh8 + wh9);

            split2(wl0, wl1, ah[s][0], al[s][0]);
            split2(wh0, wh1, ah[s][1], al[s][1]);
            split2(wl8, wl9, ah[s][2], al[s][2]);
            split2(wh8, wh9, ah[s][3], al[s][3]);
        }
        __syncthreads();

        // ldmatrix B fragments + 48 mma per chunk (3-term exact split)
#pragma unroll
        for (int s = 0; s < 2; s++) {
            const int kr = s * 16 + (lane & 15);
            const int nc = ((lane >> 4) << 3);
#pragma unroll
            for (int n16 = 0; n16 < 4; n16++) {
                uint32_t bh0, bh1, bh2, bh3, bl0, bl1, bl2, bl3;
                ldsm4t(bh0, bh1, bh2, bh3, &Bs[buf][0][kr][n16 * 16 + nc]);
                ldsm4t(bl0, bl1, bl2, bl3, &Bs[buf][1][kr][n16 * 16 + nc]);
                mma16816(c[n16 * 2],     ah[s], bh0, bh1);
                mma16816(c[n16 * 2],     al[s], bh0, bh1);
                mma16816(c[n16 * 2],     ah[s], bl0, bl1);
                mma16816(c[n16 * 2 + 1], ah[s], bh2, bh3);
                mma16816(c[n16 * 2 + 1], al[s], bh2, bh3);
                mma16816(c[n16 * 2 + 1], ah[s], bl2, bl3);
            }
        }

        // rotate prefetched values
#pragma unroll
        for (int q = 0; q < 8; q++) av[q] = nav[q];
        f2e_c = nf2e;
        f2s_c = nf2s;
        bhv0 = nbh0; bhv1 = nbh1;
        blv0 = nbl0; blv1 = nbl1;
    }

    // ---- softmax denominators (reduce over the 4 lanes sharing a row) ----
    dlo += __shfl_xor_sync(0xffffffffu, dlo, 1);
    dlo += __shfl_xor_sync(0xffffffffu, dlo, 2);
    dhi += __shfl_xor_sync(0xffffffffu, dhi, 1);
    dhi += __shfl_xor_sync(0xffffffffu, dhi, 2);
    const float rlo = __fdividef(1.f, dlo);
    const float rhi = __fdividef(1.f, dhi);

    float* olo = out + (size_t)(base + i0 + r_lo) * HID;
    float* ohi = out + (size_t)(base + i0 + r_hi) * HID;
#pragma unroll
    for (int nt = 0; nt < 8; nt++) {
        *(float2*)&olo[nt * 8 + 2 * tg] = make_float2(c[nt][0] * rlo, c[nt][1] * rlo);
        *(float2*)&ohi[nt * 8 + 2 * tg] = make_float2(c[nt][2] * rhi, c[nt][3] * rhi);
    }
}

// ---------------------------------------------------------------------------
extern "C" void kernel_launch(void* const* d_in, const int* in_sizes, int n_in,
                              void* d_out, int out_size) {
    const float* X  = (const float*)d_in[0];   // node_features [8,2048,256]
    const int*   A  = (const int*)d_in[1];     // adj [8,2048,2048]
    const float* W  = (const float*)d_in[2];   // W [256,64]
    const float* av = (const float*)d_in[3];   // a [128,1]
    float* out = (float*)d_out;                // [8,2048,64] f32

    gemm_wh<<<(B_ * N_) / 64, 256>>>(X, W);
    compute_f<<<(B_ * N_) / 8, 256>>>(av);
    gat_main<<<dim3(B_ * (N_ / TI)), 128>>>(A, out);
}

// round 6
// speedup vs baseline: 1.1974x; 1.1974x over previous
#include <cuda_runtime.h>
#include <cuda_fp16.h>
#include <cstdint>

#define B_   8
#define N_   2048
#define DIN  256
#define HID  64
#define TI   128
#define CH   32
#define NCH  (N_ / CH)
#define L2E  1.4426950408889634f

// Scratch (device globals — no allocation allowed)
__device__ float    g_Wh[B_ * N_ * HID];            // fp32 row-major (for compute_f)
__device__ uint32_t g_Whh[B_ * N_ * HID / 2];       // fp16x2 Wh  [node][h/2]
__device__ float g_f1e[B_ * N_], g_f1s[B_ * N_];    // f1*log2e, 0.2*f1*log2e
__device__ float g_f2e[B_ * N_], g_f2s[B_ * N_];

// ---------------- helpers ----------------
static __device__ __forceinline__ uint32_t smem_u32(const void* p) {
    uint32_t a;
    asm("{ .reg .u64 t; cvta.to.shared.u64 t, %1; cvt.u32.u64 %0, t; }"
        : "=r"(a) : "l"(p));
    return a;
}
static __device__ __forceinline__ float ex2(float x) {
    float y;
    asm("ex2.approx.f32 %0, %1;" : "=f"(y) : "f"(x));
    return y;
}
// pack two fp32 -> fp16x2 (w0 -> low half, w1 -> high half)
static __device__ __forceinline__ uint32_t pack2h(float w0, float w1) {
    uint32_t r;
    asm("cvt.rn.f16x2.f32 %0, %1, %2;" : "=r"(r) : "f"(w1), "f"(w0));
    return r;
}
// split pair into fp16 hi + fp16 lo (residual ~2^-22 of w)
static __device__ __forceinline__ void split2h(float w0, float w1,
                                               uint32_t& hi, uint32_t& lo) {
    uint32_t h = pack2h(w0, w1);
    float h0, h1;
    asm("{ .reg .f16 a,b; mov.b32 {a,b}, %2; cvt.f32.f16 %0, a; cvt.f32.f16 %1, b; }"
        : "=f"(h0), "=f"(h1) : "r"(h));
    lo = pack2h(w0 - h0, w1 - h1);
    hi = h;
}
static __device__ __forceinline__ void ldsm4t(uint32_t& r0, uint32_t& r1,
                                              uint32_t& r2, uint32_t& r3,
                                              const void* p) {
    uint32_t a = smem_u32(p);
    asm volatile("ldmatrix.sync.aligned.m8n8.x4.trans.shared.b16 {%0,%1,%2,%3}, [%4];"
                 : "=r"(r0), "=r"(r1), "=r"(r2), "=r"(r3) : "r"(a));
}
static __device__ __forceinline__ void mma16816(float* c, const uint32_t* a,
                                                uint32_t b0, uint32_t b1) {
    asm volatile(
        "mma.sync.aligned.m16n8k16.row.col.f32.f16.f16.f32 "
        "{%0,%1,%2,%3}, {%4,%5,%6,%7}, {%8,%9}, {%0,%1,%2,%3};"
        : "+f"(c[0]), "+f"(c[1]), "+f"(c[2]), "+f"(c[3])
        : "r"(a[0]), "r"(a[1]), "r"(a[2]), "r"(a[3]), "r"(b0), "r"(b1));
}

// ---------------------------------------------------------------------------
// Kernel A: Wh = X @ W ; emits fp32 Wh + packed fp16x2 copy.
// ---------------------------------------------------------------------------
__global__ __launch_bounds__(256) void gemm_wh(const float* __restrict__ X,
                                               const float* __restrict__ W) {
    __shared__ __align__(16) float Xs[2][64][36];
    __shared__ __align__(16) float Ws[2][32][64];

    const int tid = threadIdx.x;
    const int tx = tid & 15;
    const int ty = tid >> 4;
    const int r0 = blockIdx.x * 64;
    const int xr = tid >> 3, xk = (tid & 7) << 2;
    const int wk = tid >> 4, wh_ = (tid & 15) << 2;

    float acc[4][4];
#pragma unroll
    for (int i = 0; i < 4; i++)
#pragma unroll
        for (int j = 0; j < 4; j++) acc[i][j] = 0.f;

    float4 xv0, xv1, wv0, wv1;
    xv0 = *(const float4*)(X + (size_t)(r0 + xr) * DIN + xk);
    xv1 = *(const float4*)(X + (size_t)(r0 + 32 + xr) * DIN + xk);
    wv0 = *(const float4*)(W + (size_t)wk * HID + wh_);
    wv1 = *(const float4*)(W + (size_t)(16 + wk) * HID + wh_);
    *(float4*)&Xs[0][xr][xk]      = xv0;
    *(float4*)&Xs[0][32 + xr][xk] = xv1;
    *(float4*)&Ws[0][wk][wh_]      = wv0;
    *(float4*)&Ws[0][16 + wk][wh_] = wv1;
    __syncthreads();

    for (int kt = 0; kt < 8; kt++) {
        const int cur = kt & 1, nxt = cur ^ 1;
        if (kt < 7) {
            const int k0 = (kt + 1) * 32;
            xv0 = *(const float4*)(X + (size_t)(r0 + xr) * DIN + k0 + xk);
            xv1 = *(const float4*)(X + (size_t)(r0 + 32 + xr) * DIN + k0 + xk);
            wv0 = *(const float4*)(W + (size_t)(k0 + wk) * HID + wh_);
            wv1 = *(const float4*)(W + (size_t)(k0 + 16 + wk) * HID + wh_);
        }
#pragma unroll
        for (int k = 0; k < 32; k++) {
            float4 wv = *(float4*)&Ws[cur][k][tx << 2];
#pragma unroll
            for (int rr = 0; rr < 4; rr++) {
                float xv = Xs[cur][(ty << 2) + rr][k];
                acc[rr][0] += xv * wv.x;
                acc[rr][1] += xv * wv.y;
                acc[rr][2] += xv * wv.z;
                acc[rr][3] += xv * wv.w;
            }
        }
        if (kt < 7) {
            *(float4*)&Xs[nxt][xr][xk]      = xv0;
            *(float4*)&Xs[nxt][32 + xr][xk] = xv1;
            *(float4*)&Ws[nxt][wk][wh_]      = wv0;
            *(float4*)&Ws[nxt][16 + wk][wh_] = wv1;
        }
        __syncthreads();
    }

#pragma unroll
    for (int rr = 0; rr < 4; rr++) {
        const int node = r0 + (ty << 2) + rr;
        float4 v = make_float4(acc[rr][0], acc[rr][1], acc[rr][2], acc[rr][3]);
        *(float4*)&g_Wh[(size_t)node * HID + (tx << 2)] = v;
        size_t o = (size_t)node * 32 + tx * 2;
        *(uint2*)&g_Whh[o] = make_uint2(pack2h(v.x, v.y), pack2h(v.z, v.w));
    }
}

// ---------------------------------------------------------------------------
// Kernel B: f1/f2 per node, pre-scaled by log2e (and 0.2*log2e).
// ---------------------------------------------------------------------------
__global__ __launch_bounds__(256) void compute_f(const float* __restrict__ a) {
    const int row = blockIdx.x * 8 + (threadIdx.x >> 5);
    const int lane = threadIdx.x & 31;
    const float* wh = g_Wh + (size_t)row * HID;
    float w0 = wh[lane], w1 = wh[lane + 32];
    float f1 = w0 * a[lane] + w1 * a[lane + 32];
    float f2 = w0 * a[HID + lane] + w1 * a[HID + lane + 32];
#pragma unroll
    for (int s = 16; s > 0; s >>= 1) {
        f1 += __shfl_xor_sync(0xffffffffu, f1, s);
        f2 += __shfl_xor_sync(0xffffffffu, f2, s);
    }
    if (lane == 0) {
        g_f1e[row] = f1 * L2E;
        g_f1s[row] = 0.2f * f1 * L2E;
        g_f2e[row] = f2 * L2E;
        g_f2s[row] = 0.2f * f2 * L2E;
    }
}

// ---------------------------------------------------------------------------
// Main kernel: masked-softmax attention * Wh via mma.sync fp16, 2-term split:
//   A (attention weights) = exact fp16 hi+lo (residual 2^-22),
//   B (Wh) = single fp16 (dropped term ~2^-11 -> rel_err ~3e-4 < 1e-3).
// TI=128, 256 threads, grid 128 (one wave; HMMA-throughput-bound).
// A fragments computed in mma register layout — never touch SMEM. B double-
// buffered in SMEM, 144B-padded rows -> conflict-free ldmatrix.x4.trans.
// ---------------------------------------------------------------------------
__global__ __launch_bounds__(256, 1) void gat_main(const int* __restrict__ adj,
                                                   float* __restrict__ out) {
    __shared__ __align__(16) __half Bs[2][CH][72];  // [buf][k][n]

    const int tid = threadIdx.x;
    const int lane = tid & 31, wid = tid >> 5;
    const int g = lane >> 2, tg = lane & 3;
    const int b = blockIdx.x >> 4;
    const int i0 = (blockIdx.x & 15) * TI;
    const int base = b * N_;

    const int r_lo = wid * 16 + g, r_hi = r_lo + 8;

    // B staging: thread covers node fj, h = fh..fh+7 (one uint4)
    const int fj = tid >> 3, fh = (tid & 7) * 8;
    const uint32_t* whh = g_Whh + (size_t)base * 32;

    const float f1e_lo = g_f1e[base + i0 + r_lo], f1s_lo = g_f1s[base + i0 + r_lo];
    const float f1e_hi = g_f1e[base + i0 + r_hi], f1s_hi = g_f1s[base + i0 + r_hi];
    float dlo = 0.f, dhi = 0.f;

    float c[8][4];
#pragma unroll
    for (int nt = 0; nt < 8; nt++)
#pragma unroll
        for (int q = 0; q < 4; q++) c[nt][q] = 0.f;

    const int* adjlo = adj + (size_t)b * N_ * N_ + (size_t)(i0 + r_lo) * N_;
    const int* adjhi = adjlo + (size_t)8 * N_;

    // ---- prefetch chunk 0 ----
    int2 av[8];
#pragma unroll
    for (int s = 0; s < 2; s++) {
        av[s * 4 + 0] = *(const int2*)&adjlo[s * 16 + 2 * tg];
        av[s * 4 + 1] = *(const int2*)&adjlo[s * 16 + 2 * tg + 8];
        av[s * 4 + 2] = *(const int2*)&adjhi[s * 16 + 2 * tg];
        av[s * 4 + 3] = *(const int2*)&adjhi[s * 16 + 2 * tg + 8];
    }
    float f2e_c = g_f2e[base + lane];
    float f2s_c = g_f2s[base + lane];
    uint4 bhv = *(const uint4*)&whh[(size_t)fj * 32 + (fh >> 1)];

#pragma unroll 2
    for (int t = 0; t < NCH; t++) {
        const int buf = t & 1;

        // store B(t) into SMEM buffer
        *(uint4*)&Bs[buf][fj][fh] = bhv;

        // issue prefetch for t+1 (latency hides under stage1 + mma)
        const int tn = (t + 1 < NCH) ? t + 1 : t;
        const int j0n = tn * CH;
        int2 nav[8];
#pragma unroll
        for (int s = 0; s < 2; s++) {
            nav[s * 4 + 0] = *(const int2*)&adjlo[j0n + s * 16 + 2 * tg];
            nav[s * 4 + 1] = *(const int2*)&adjlo[j0n + s * 16 + 2 * tg + 8];
            nav[s * 4 + 2] = *(const int2*)&adjhi[j0n + s * 16 + 2 * tg];
            nav[s * 4 + 3] = *(const int2*)&adjhi[j0n + s * 16 + 2 * tg + 8];
        }
        float nf2e = g_f2e[base + j0n + lane];
        float nf2s = g_f2s[base + j0n + lane];
        uint4 nbh = *(const uint4*)&whh[(size_t)(j0n + fj) * 32 + (fh >> 1)];

        // stage1: attention-weight A-fragments (fp16 hi/lo) in mma layout
        uint32_t ah[2][4], al[2][4];
#pragma unroll
        for (int s = 0; s < 2; s++) {
            const int jb = s * 16 + 2 * tg;
            float e0 = __shfl_sync(0xffffffffu, f2e_c, jb);
            float e1 = __shfl_sync(0xffffffffu, f2e_c, jb + 1);
            float e8 = __shfl_sync(0xffffffffu, f2e_c, jb + 8);
            float e9 = __shfl_sync(0xffffffffu, f2e_c, jb + 9);
            float s0 = __shfl_sync(0xffffffffu, f2s_c, jb);
            float s1 = __shfl_sync(0xffffffffu, f2s_c, jb + 1);
            float s8 = __shfl_sync(0xffffffffu, f2s_c, jb + 8);
            float s9 = __shfl_sync(0xffffffffu, f2s_c, jb + 9);

            float wl0 = (av[s * 4 + 0].x > 0) ? ex2(fmaxf(f1e_lo + e0, f1s_lo + s0)) : 0.f;
            float wl1 = (av[s * 4 + 0].y > 0) ? ex2(fmaxf(f1e_lo + e1, f1s_lo + s1)) : 0.f;
            float wl8 = (av[s * 4 + 1].x > 0) ? ex2(fmaxf(f1e_lo + e8, f1s_lo + s8)) : 0.f;
            float wl9 = (av[s * 4 + 1].y > 0) ? ex2(fmaxf(f1e_lo + e9, f1s_lo + s9)) : 0.f;
            float wh0 = (av[s * 4 + 2].x > 0) ? ex2(fmaxf(f1e_hi + e0, f1s_hi + s0)) : 0.f;
            float wh1 = (av[s * 4 + 2].y > 0) ? ex2(fmaxf(f1e_hi + e1, f1s_hi + s1)) : 0.f;
            float wh8 = (av[s * 4 + 3].x > 0) ? ex2(fmaxf(f1e_hi + e8, f1s_hi + s8)) : 0.f;
            float wh9 = (av[s * 4 + 3].y > 0) ? ex2(fmaxf(f1e_hi + e9, f1s_hi + s9)) : 0.f;

            dlo += (wl0 + wl1) + (wl8 + wl9);
            dhi += (wh0 + wh1) + (wh8 + wh9);

            split2h(wl0, wl1, ah[s][0], al[s][0]);
            split2h(wh0, wh1, ah[s][1], al[s][1]);
            split2h(wl8, wl9, ah[s][2], al[s][2]);
            split2h(wh8, wh9, ah[s][3], al[s][3]);
        }
        __syncthreads();

        // ldmatrix B fragments + 32 mma per chunk (A hi/lo x B)
#pragma unroll
        for (int s = 0; s < 2; s++) {
            const int kr = s * 16 + (lane & 15);
            const int nc = ((lane >> 4) << 3);
#pragma unroll
            for (int n16 = 0; n16 < 4; n16++) {
                uint32_t b0, b1, b2, b3;
                ldsm4t(b0, b1, b2, b3, &Bs[buf][kr][n16 * 16 + nc]);
                mma16816(c[n16 * 2],     ah[s], b0, b1);
                mma16816(c[n16 * 2],     al[s], b0, b1);
                mma16816(c[n16 * 2 + 1], ah[s], b2, b3);
                mma16816(c[n16 * 2 + 1], al[s], b2, b3);
            }
        }

        // rotate prefetched values
#pragma unroll
        for (int q = 0; q < 8; q++) av[q] = nav[q];
        f2e_c = nf2e;
        f2s_c = nf2s;
        bhv = nbh;
    }

    // ---- softmax denominators (reduce over the 4 lanes sharing a row) ----
    dlo += __shfl_xor_sync(0xffffffffu, dlo, 1);
    dlo += __shfl_xor_sync(0xffffffffu, dlo, 2);
    dhi += __shfl_xor_sync(0xffffffffu, dhi, 1);
    dhi += __shfl_xor_sync(0xffffffffu, dhi, 2);
    const float rlo = __fdividef(1.f, dlo);
    const float rhi = __fdividef(1.f, dhi);

    float* olo = out + (size_t)(base + i0 + r_lo) * HID;
    float* ohi = out + (size_t)(base + i0 + r_hi) * HID;
#pragma unroll
    for (int nt = 0; nt < 8; nt++) {
        *(float2*)&olo[nt * 8 + 2 * tg] = make_float2(c[nt][0] * rlo, c[nt][1] * rlo);
        *(float2*)&ohi[nt * 8 + 2 * tg] = make_float2(c[nt][2] * rhi, c[nt][3] * rhi);
    }
}

// ---------------------------------------------------------------------------
extern "C" void kernel_launch(void* const* d_in, const int* in_sizes, int n_in,
                              void* d_out, int out_size) {
    const float* X  = (const float*)d_in[0];   // node_features [8,2048,256]
    const int*   A  = (const int*)d_in[1];     // adj [8,2048,2048]
    const float* W  = (const float*)d_in[2];   // W [256,64]
    const float* av = (const float*)d_in[3];   // a [128,1]
    float* out = (float*)d_out;                // [8,2048,64] f32

    gemm_wh<<<(B_ * N_) / 64, 256>>>(X, W);
    compute_f<<<(B_ * N_) / 8, 256>>>(av);
    gat_main<<<dim3(B_ * (N_ / TI)), 256>>>(A, out);
}

// round 7
// speedup vs baseline: 1.3802x; 1.1527x over previous
#include <cuda_runtime.h>
#include <cuda_fp16.h>
#include <cstdint>

#define B_   8
#define N_   2048
#define DIN  256
#define HID  64
#define TI   128
#define CH   32
#define NCH  (N_ / CH)
#define L2E  1.4426950408889634f

// Scratch (device globals — no allocation allowed)
__device__ uint32_t g_Whh[B_ * N_ * HID / 2];       // fp16x2 Wh  [node][h/2]
__device__ float g_f1e[B_ * N_], g_f1s[B_ * N_];    // f1*log2e, 0.2*f1*log2e
__device__ float g_f2e[B_ * N_], g_f2s[B_ * N_];

// ---------------- helpers ----------------
static __device__ __forceinline__ uint32_t smem_u32(const void* p) {
    uint32_t a;
    asm("{ .reg .u64 t; cvta.to.shared.u64 t, %1; cvt.u32.u64 %0, t; }"
        : "=r"(a) : "l"(p));
    return a;
}
static __device__ __forceinline__ float ex2(float x) {
    float y;
    asm("ex2.approx.f32 %0, %1;" : "=f"(y) : "f"(x));
    return y;
}
// pack two fp32 -> fp16x2 (w0 -> low half, w1 -> high half)
static __device__ __forceinline__ uint32_t pack2h(float w0, float w1) {
    uint32_t r;
    asm("cvt.rn.f16x2.f32 %0, %1, %2;" : "=r"(r) : "f"(w1), "f"(w0));
    return r;
}
static __device__ __forceinline__ void ldsm4t(uint32_t& r0, uint32_t& r1,
                                              uint32_t& r2, uint32_t& r3,
                                              const void* p) {
    uint32_t a = smem_u32(p);
    asm volatile("ldmatrix.sync.aligned.m8n8.x4.trans.shared.b16 {%0,%1,%2,%3}, [%4];"
                 : "=r"(r0), "=r"(r1), "=r"(r2), "=r"(r3) : "r"(a));
}
static __device__ __forceinline__ void mma16816(float* c, const uint32_t* a,
                                                uint32_t b0, uint32_t b1) {
    asm volatile(
        "mma.sync.aligned.m16n8k16.row.col.f32.f16.f16.f32 "
        "{%0,%1,%2,%3}, {%4,%5,%6,%7}, {%8,%9}, {%0,%1,%2,%3};"
        : "+f"(c[0]), "+f"(c[1]), "+f"(c[2]), "+f"(c[3])
        : "r"(a[0]), "r"(a[1]), "r"(a[2]), "r"(a[3]), "r"(b0), "r"(b1));
}

// ---------------------------------------------------------------------------
// Kernel A: Wh = X @ W ; emits packed fp16x2 Wh AND the per-node f1/f2
// exponent factors (fused former compute_f — fp32 g_Wh never materialized).
// ---------------------------------------------------------------------------
__global__ __launch_bounds__(256) void gemm_wh(const float* __restrict__ X,
                                               const float* __restrict__ W,
                                               const float* __restrict__ a) {
    __shared__ __align__(16) float Xs[2][64][36];
    __shared__ __align__(16) float Ws[2][32][64];

    const int tid = threadIdx.x;
    const int tx = tid & 15;
    const int ty = tid >> 4;
    const int r0 = blockIdx.x * 64;
    const int xr = tid >> 3, xk = (tid & 7) << 2;
    const int wk = tid >> 4, wh_ = (tid & 15) << 2;

    float acc[4][4];
#pragma unroll
    for (int i = 0; i < 4; i++)
#pragma unroll
        for (int j = 0; j < 4; j++) acc[i][j] = 0.f;

    float4 xv0, xv1, wv0, wv1;
    xv0 = *(const float4*)(X + (size_t)(r0 + xr) * DIN + xk);
    xv1 = *(const float4*)(X + (size_t)(r0 + 32 + xr) * DIN + xk);
    wv0 = *(const float4*)(W + (size_t)wk * HID + wh_);
    wv1 = *(const float4*)(W + (size_t)(16 + wk) * HID + wh_);
    *(float4*)&Xs[0][xr][xk]      = xv0;
    *(float4*)&Xs[0][32 + xr][xk] = xv1;
    *(float4*)&Ws[0][wk][wh_]      = wv0;
    *(float4*)&Ws[0][16 + wk][wh_] = wv1;
    __syncthreads();

    for (int kt = 0; kt < 8; kt++) {
        const int cur = kt & 1, nxt = cur ^ 1;
        if (kt < 7) {
            const int k0 = (kt + 1) * 32;
            xv0 = *(const float4*)(X + (size_t)(r0 + xr) * DIN + k0 + xk);
            xv1 = *(const float4*)(X + (size_t)(r0 + 32 + xr) * DIN + k0 + xk);
            wv0 = *(const float4*)(W + (size_t)(k0 + wk) * HID + wh_);
            wv1 = *(const float4*)(W + (size_t)(k0 + 16 + wk) * HID + wh_);
        }
#pragma unroll
        for (int k = 0; k < 32; k++) {
            float4 wv = *(float4*)&Ws[cur][k][tx << 2];
#pragma unroll
            for (int rr = 0; rr < 4; rr++) {
                float xv = Xs[cur][(ty << 2) + rr][k];
                acc[rr][0] += xv * wv.x;
                acc[rr][1] += xv * wv.y;
                acc[rr][2] += xv * wv.z;
                acc[rr][3] += xv * wv.w;
            }
        }
        if (kt < 7) {
            *(float4*)&Xs[nxt][xr][xk]      = xv0;
            *(float4*)&Xs[nxt][32 + xr][xk] = xv1;
            *(float4*)&Ws[nxt][wk][wh_]      = wv0;
            *(float4*)&Ws[nxt][16 + wk][wh_] = wv1;
        }
        __syncthreads();
    }

    // fp16 Wh output
#pragma unroll
    for (int rr = 0; rr < 4; rr++) {
        const int node = r0 + (ty << 2) + rr;
        size_t o = (size_t)node * 32 + tx * 2;
        *(uint2*)&g_Whh[o] = make_uint2(pack2h(acc[rr][0], acc[rr][1]),
                                        pack2h(acc[rr][2], acc[rr][3]));
    }

    // fused f1/f2 epilogue: partial dot over this thread's 4 h-cols, then
    // half-warp (16-lane, same ty) shfl reduction across tx.
    const float4 a1 = *(const float4*)(a + (tx << 2));
    const float4 a2 = *(const float4*)(a + HID + (tx << 2));
    float p1[4], p2[4];
#pragma unroll
    for (int rr = 0; rr < 4; rr++) {
        p1[rr] = acc[rr][0] * a1.x + acc[rr][1] * a1.y +
                 acc[rr][2] * a1.z + acc[rr][3] * a1.w;
        p2[rr] = acc[rr][0] * a2.x + acc[rr][1] * a2.y +
                 acc[rr][2] * a2.z + acc[rr][3] * a2.w;
#pragma unroll
        for (int s = 8; s > 0; s >>= 1) {
            p1[rr] += __shfl_xor_sync(0xffffffffu, p1[rr], s);
            p2[rr] += __shfl_xor_sync(0xffffffffu, p2[rr], s);
        }
    }
    if (tx == 0) {
#pragma unroll
        for (int rr = 0; rr < 4; rr++) {
            const int node = r0 + (ty << 2) + rr;
            g_f1e[node] = p1[rr] * L2E;
            g_f1s[node] = 0.2f * p1[rr] * L2E;
            g_f2e[node] = p2[rr] * L2E;
            g_f2s[node] = 0.2f * p2[rr] * L2E;
        }
    }
}

// ---------------------------------------------------------------------------
// Main kernel: masked-softmax attention * Wh via mma.sync fp16.
//   A (attention weights): computed exactly in fp32 (fp32 ex2), rounded once
//     to fp16 (per-element ~2^-12 rms, same scale as B's rounding).
//   B (Wh): single fp16.  16 mma per chunk.
// f2e/f2s for the whole batch staged in SMEM once (no shfl transport).
// TI=128, 256 threads, grid 128 (one wave; HMMA-throughput-bound).
// ---------------------------------------------------------------------------
__global__ __launch_bounds__(256, 1) void gat_main(const int* __restrict__ adj,
                                                   float* __restrict__ out) {
    __shared__ __align__(16) __half Bs[2][CH][72];  // [buf][k][n]
    __shared__ __align__(16) float f2e_s[N_];
    __shared__ __align__(16) float f2s_s[N_];

    const int tid = threadIdx.x;
    const int lane = tid & 31, wid = tid >> 5;
    const int g = lane >> 2, tg = lane & 3;
    const int b = blockIdx.x >> 4;
    const int i0 = (blockIdx.x & 15) * TI;
    const int base = b * N_;

    const int r_lo = wid * 16 + g, r_hi = r_lo + 8;

    // stage f2e/f2s for the whole batch into SMEM (once)
#pragma unroll
    for (int q = 0; q < N_ / 4 / 256; q++) {
        const int idx = (q * 256 + tid) * 4;
        *(float4*)&f2e_s[idx] = *(const float4*)(g_f2e + base + idx);
        *(float4*)&f2s_s[idx] = *(const float4*)(g_f2s + base + idx);
    }

    // B staging: thread covers node fj, h = fh..fh+7 (one uint4)
    const int fj = tid >> 3, fh = (tid & 7) * 8;
    const uint32_t* whh = g_Whh + (size_t)base * 32;

    const float f1e_lo = g_f1e[base + i0 + r_lo], f1s_lo = g_f1s[base + i0 + r_lo];
    const float f1e_hi = g_f1e[base + i0 + r_hi], f1s_hi = g_f1s[base + i0 + r_hi];
    float dlo = 0.f, dhi = 0.f;

    float c[8][4];
#pragma unroll
    for (int nt = 0; nt < 8; nt++)
#pragma unroll
        for (int q = 0; q < 4; q++) c[nt][q] = 0.f;

    const int* adjlo = adj + (size_t)b * N_ * N_ + (size_t)(i0 + r_lo) * N_;
    const int* adjhi = adjlo + (size_t)8 * N_;

    // ---- prefetch chunk 0 (adj + B tile) ----
    int2 av[8];
#pragma unroll
    for (int s = 0; s < 2; s++) {
        av[s * 4 + 0] = *(const int2*)&adjlo[s * 16 + 2 * tg];
        av[s * 4 + 1] = *(const int2*)&adjlo[s * 16 + 2 * tg + 8];
        av[s * 4 + 2] = *(const int2*)&adjhi[s * 16 + 2 * tg];
        av[s * 4 + 3] = *(const int2*)&adjhi[s * 16 + 2 * tg + 8];
    }
    uint4 bhv = *(const uint4*)&whh[(size_t)fj * 32 + (fh >> 1)];

    __syncthreads();  // f2e_s/f2s_s visible

#pragma unroll 2
    for (int t = 0; t < NCH; t++) {
        const int buf = t & 1;

        // store B(t) into SMEM buffer
        *(uint4*)&Bs[buf][fj][fh] = bhv;

        // issue prefetch for t+1 (latency hides under stage1 + mma)
        const int tn = (t + 1 < NCH) ? t + 1 : t;
        const int j0n = tn * CH;
        int2 nav[8];
#pragma unroll
        for (int s = 0; s < 2; s++) {
            nav[s * 4 + 0] = *(const int2*)&adjlo[j0n + s * 16 + 2 * tg];
            nav[s * 4 + 1] = *(const int2*)&adjlo[j0n + s * 16 + 2 * tg + 8];
            nav[s * 4 + 2] = *(const int2*)&adjhi[j0n + s * 16 + 2 * tg];
            nav[s * 4 + 3] = *(const int2*)&adjhi[j0n + s * 16 + 2 * tg + 8];
        }
        uint4 nbh = *(const uint4*)&whh[(size_t)(j0n + fj) * 32 + (fh >> 1)];

        // stage1: attention-weight A-fragments (fp32 math, one fp16 rounding)
        uint32_t ah[2][4];
#pragma unroll
        for (int s = 0; s < 2; s++) {
            const int jb = t * CH + s * 16 + 2 * tg;
            const float2 e01 = *(const float2*)&f2e_s[jb];
            const float2 e89 = *(const float2*)&f2e_s[jb + 8];
            const float2 s01 = *(const float2*)&f2s_s[jb];
            const float2 s89 = *(const float2*)&f2s_s[jb + 8];

            float wl0 = (av[s * 4 + 0].x > 0) ? ex2(fmaxf(f1e_lo + e01.x, f1s_lo + s01.x)) : 0.f;
            float wl1 = (av[s * 4 + 0].y > 0) ? ex2(fmaxf(f1e_lo + e01.y, f1s_lo + s01.y)) : 0.f;
            float wl8 = (av[s * 4 + 1].x > 0) ? ex2(fmaxf(f1e_lo + e89.x, f1s_lo + s89.x)) : 0.f;
            float wl9 = (av[s * 4 + 1].y > 0) ? ex2(fmaxf(f1e_lo + e89.y, f1s_lo + s89.y)) : 0.f;
            float wh0 = (av[s * 4 + 2].x > 0) ? ex2(fmaxf(f1e_hi + e01.x, f1s_hi + s01.x)) : 0.f;
            float wh1 = (av[s * 4 + 2].y > 0) ? ex2(fmaxf(f1e_hi + e01.y, f1s_hi + s01.y)) : 0.f;
            float wh8 = (av[s * 4 + 3].x > 0) ? ex2(fmaxf(f1e_hi + e89.x, f1s_hi + s89.x)) : 0.f;
            float wh9 = (av[s * 4 + 3].y > 0) ? ex2(fmaxf(f1e_hi + e89.y, f1s_hi + s89.y)) : 0.f;

            dlo += (wl0 + wl1) + (wl8 + wl9);
            dhi += (wh0 + wh1) + (wh8 + wh9);

            ah[s][0] = pack2h(wl0, wl1);
            ah[s][1] = pack2h(wh0, wh1);
            ah[s][2] = pack2h(wl8, wl9);
            ah[s][3] = pack2h(wh8, wh9);
        }
        __syncthreads();

        // ldmatrix B fragments + 16 mma per chunk
#pragma unroll
        for (int s = 0; s < 2; s++) {
            const int kr = s * 16 + (lane & 15);
            const int nc = ((lane >> 4) << 3);
#pragma unroll
            for (int n16 = 0; n16 < 4; n16++) {
                uint32_t b0, b1, b2, b3;
                ldsm4t(b0, b1, b2, b3, &Bs[buf][kr][n16 * 16 + nc]);
                mma16816(c[n16 * 2],     ah[s], b0, b1);
                mma16816(c[n16 * 2 + 1], ah[s], b2, b3);
            }
        }

        // rotate prefetched values
#pragma unroll
        for (int q = 0; q < 8; q++) av[q] = nav[q];
        bhv = nbh;
    }

    // ---- softmax denominators (reduce over the 4 lanes sharing a row) ----
    dlo += __shfl_xor_sync(0xffffffffu, dlo, 1);
    dlo += __shfl_xor_sync(0xffffffffu, dlo, 2);
    dhi += __shfl_xor_sync(0xffffffffu, dhi, 1);
    dhi += __shfl_xor_sync(0xffffffffu, dhi, 2);
    const float rlo = __fdividef(1.f, dlo);
    const float rhi = __fdividef(1.f, dhi);

    float* olo = out + (size_t)(base + i0 + r_lo) * HID;
    float* ohi = out + (size_t)(base + i0 + r_hi) * HID;
#pragma unroll
    for (int nt = 0; nt < 8; nt++) {
        *(float2*)&olo[nt * 8 + 2 * tg] = make_float2(c[nt][0] * rlo, c[nt][1] * rlo);
        *(float2*)&ohi[nt * 8 + 2 * tg] = make_float2(c[nt][2] * rhi, c[nt][3] * rhi);
    }
}

// ---------------------------------------------------------------------------
extern "C" void kernel_launch(void* const* d_in, const int* in_sizes, int n_in,
                              void* d_out, int out_size) {
    const float* X  = (const float*)d_in[0];   // node_features [8,2048,256]
    const int*   A  = (const int*)d_in[1];     // adj [8,2048,2048]
    const float* W  = (const float*)d_in[2];   // W [256,64]
    const float* av = (const float*)d_in[3];   // a [128,1]
    float* out = (float*)d_out;                // [8,2048,64] f32

    gemm_wh<<<(B_ * N_) / 64, 256>>>(X, W, av);
    gat_main<<<dim3(B_ * (N_ / TI)), 256>>>(A, out);
}

// round 8
// speedup vs baseline: 1.5712x; 1.1384x over previous
#include <cuda_runtime.h>
#include <cuda_fp16.h>
#include <cstdint>

#define B_   8
#define N_   2048
#define DIN  256
#define HID  64
#define TI   128
#define CH   32
#define NCH  (N_ / CH)
#define L2E  1.4426950408889634f

// dynamic SMEM layout for gat_main
#define SLOT_A  (128 * 144)                 // adj tile: 128 rows x 32 ints, 144B-padded
#define AOFF    0
#define BOFF    (4 * SLOT_A)                // 73728
#define SLOT_B  (32 * 144)                  // B tile: 32 nodes x 64 fp16, 144B-padded
#define F2EOFF  (BOFF + 4 * SLOT_B)         // 92160
#define F2SOFF  (F2EOFF + N_ * 4)           // 100352
#define SMEM_DYN (F2SOFF + N_ * 4)          // 108544

// Scratch (device globals — no allocation allowed)
__device__ uint32_t g_Whh[B_ * N_ * HID / 2];       // fp16x2 Wh  [node][h/2]
__device__ float g_f1e[B_ * N_], g_f1s[B_ * N_];    // f1*log2e, 0.2*f1*log2e
__device__ float g_f2e[B_ * N_], g_f2s[B_ * N_];

// ---------------- helpers ----------------
static __device__ __forceinline__ uint32_t smem_u32(const void* p) {
    uint32_t a;
    asm("{ .reg .u64 t; cvta.to.shared.u64 t, %1; cvt.u32.u64 %0, t; }"
        : "=r"(a) : "l"(p));
    return a;
}
static __device__ __forceinline__ float ex2(float x) {
    float y;
    asm("ex2.approx.f32 %0, %1;" : "=f"(y) : "f"(x));
    return y;
}
static __device__ __forceinline__ uint32_t pack2h(float w0, float w1) {
    uint32_t r;
    asm("cvt.rn.f16x2.f32 %0, %1, %2;" : "=r"(r) : "f"(w1), "f"(w0));
    return r;
}
static __device__ __forceinline__ void ldsm4t(uint32_t& r0, uint32_t& r1,
                                              uint32_t& r2, uint32_t& r3,
                                              const void* p) {
    uint32_t a = smem_u32(p);
    asm volatile("ldmatrix.sync.aligned.m8n8.x4.trans.shared.b16 {%0,%1,%2,%3}, [%4];"
                 : "=r"(r0), "=r"(r1), "=r"(r2), "=r"(r3) : "r"(a));
}
static __device__ __forceinline__ void mma16816(float* c, const uint32_t* a,
                                                uint32_t b0, uint32_t b1) {
    asm volatile(
        "mma.sync.aligned.m16n8k16.row.col.f32.f16.f16.f32 "
        "{%0,%1,%2,%3}, {%4,%5,%6,%7}, {%8,%9}, {%0,%1,%2,%3};"
        : "+f"(c[0]), "+f"(c[1]), "+f"(c[2]), "+f"(c[3])
        : "r"(a[0]), "r"(a[1]), "r"(a[2]), "r"(a[3]), "r"(b0), "r"(b1));
}
#define CP_ASYNC16(dst, src) \
    asm volatile("cp.async.cg.shared.global [%0], [%1], 16;" :: "r"(dst), "l"(src) : "memory")
#define CP_COMMIT()  asm volatile("cp.async.commit_group;" ::: "memory")
#define CP_WAIT2()   asm volatile("cp.async.wait_group 2;" ::: "memory")

// ---------------------------------------------------------------------------
// Kernel A: Wh = X @ W ; emits packed fp16x2 Wh AND per-node f1/f2 factors.
// 2 CTAs/SM for latency hiding.
// ---------------------------------------------------------------------------
__global__ __launch_bounds__(256, 2) void gemm_wh(const float* __restrict__ X,
                                                  const float* __restrict__ W,
                                                  const float* __restrict__ a) {
    __shared__ __align__(16) float Xs[2][64][36];
    __shared__ __align__(16) float Ws[2][32][64];

    const int tid = threadIdx.x;
    const int tx = tid & 15;
    const int ty = tid >> 4;
    const int r0 = blockIdx.x * 64;
    const int xr = tid >> 3, xk = (tid & 7) << 2;
    const int wk = tid >> 4, wh_ = (tid & 15) << 2;

    float acc[4][4];
#pragma unroll
    for (int i = 0; i < 4; i++)
#pragma unroll
        for (int j = 0; j < 4; j++) acc[i][j] = 0.f;

    float4 xv0, xv1, wv0, wv1;
    xv0 = *(const float4*)(X + (size_t)(r0 + xr) * DIN + xk);
    xv1 = *(const float4*)(X + (size_t)(r0 + 32 + xr) * DIN + xk);
    wv0 = *(const float4*)(W + (size_t)wk * HID + wh_);
    wv1 = *(const float4*)(W + (size_t)(16 + wk) * HID + wh_);
    *(float4*)&Xs[0][xr][xk]      = xv0;
    *(float4*)&Xs[0][32 + xr][xk] = xv1;
    *(float4*)&Ws[0][wk][wh_]      = wv0;
    *(float4*)&Ws[0][16 + wk][wh_] = wv1;
    __syncthreads();

    for (int kt = 0; kt < 8; kt++) {
        const int cur = kt & 1, nxt = cur ^ 1;
        if (kt < 7) {
            const int k0 = (kt + 1) * 32;
            xv0 = *(const float4*)(X + (size_t)(r0 + xr) * DIN + k0 + xk);
            xv1 = *(const float4*)(X + (size_t)(r0 + 32 + xr) * DIN + k0 + xk);
            wv0 = *(const float4*)(W + (size_t)(k0 + wk) * HID + wh_);
            wv1 = *(const float4*)(W + (size_t)(k0 + 16 + wk) * HID + wh_);
        }
#pragma unroll
        for (int k = 0; k < 32; k++) {
            float4 wv = *(float4*)&Ws[cur][k][tx << 2];
#pragma unroll
            for (int rr = 0; rr < 4; rr++) {
                float xv = Xs[cur][(ty << 2) + rr][k];
                acc[rr][0] += xv * wv.x;
                acc[rr][1] += xv * wv.y;
                acc[rr][2] += xv * wv.z;
                acc[rr][3] += xv * wv.w;
            }
        }
        if (kt < 7) {
            *(float4*)&Xs[nxt][xr][xk]      = xv0;
            *(float4*)&Xs[nxt][32 + xr][xk] = xv1;
            *(float4*)&Ws[nxt][wk][wh_]      = wv0;
            *(float4*)&Ws[nxt][16 + wk][wh_] = wv1;
        }
        __syncthreads();
    }

    // fp16 Wh output
#pragma unroll
    for (int rr = 0; rr < 4; rr++) {
        const int node = r0 + (ty << 2) + rr;
        size_t o = (size_t)node * 32 + tx * 2;
        *(uint2*)&g_Whh[o] = make_uint2(pack2h(acc[rr][0], acc[rr][1]),
                                        pack2h(acc[rr][2], acc[rr][3]));
    }

    // fused f1/f2 epilogue
    const float4 a1 = *(const float4*)(a + (tx << 2));
    const float4 a2 = *(const float4*)(a + HID + (tx << 2));
    float p1[4], p2[4];
#pragma unroll
    for (int rr = 0; rr < 4; rr++) {
        p1[rr] = acc[rr][0] * a1.x + acc[rr][1] * a1.y +
                 acc[rr][2] * a1.z + acc[rr][3] * a1.w;
        p2[rr] = acc[rr][0] * a2.x + acc[rr][1] * a2.y +
                 acc[rr][2] * a2.z + acc[rr][3] * a2.w;
#pragma unroll
        for (int s = 8; s > 0; s >>= 1) {
            p1[rr] += __shfl_xor_sync(0xffffffffu, p1[rr], s);
            p2[rr] += __shfl_xor_sync(0xffffffffu, p2[rr], s);
        }
    }
    if (tx == 0) {
#pragma unroll
        for (int rr = 0; rr < 4; rr++) {
            const int node = r0 + (ty << 2) + rr;
            g_f1e[node] = p1[rr] * L2E;
            g_f1s[node] = 0.2f * p1[rr] * L2E;
            g_f2e[node] = p2[rr] * L2E;
            g_f2s[node] = 0.2f * p2[rr] * L2E;
        }
    }
}

// ---------------------------------------------------------------------------
// Main kernel: masked-softmax attention * Wh via mma.sync fp16.
// Deep cp.async pipeline: 4-slot SMEM ring for adj (16KB/chunk) + B (4KB),
// 3 chunks in flight -> high MLP for the 134MB adj stream. Stage1 reads adj
// from SMEM; A frags in fp32 then one fp16 rounding; 16 HMMA per chunk.
// ---------------------------------------------------------------------------
__global__ __launch_bounds__(256) void gat_main(const int* __restrict__ adj,
                                                float* __restrict__ out) {
    extern __shared__ __align__(16) char sm[];
    const uint32_t smb = smem_u32(sm);
    float* f2e_s = (float*)(sm + F2EOFF);
    float* f2s_s = (float*)(sm + F2SOFF);

    const int tid = threadIdx.x;
    const int lane = tid & 31, wid = tid >> 5;
    const int g = lane >> 2, tg = lane & 3;
    const int b = blockIdx.x >> 4;
    const int i0 = (blockIdx.x & 15) * TI;
    const int base = b * N_;

    const int r_lo = wid * 16 + g, r_hi = r_lo + 8;

    const int* adjb = adj + (size_t)b * N_ * N_ + (size_t)i0 * N_;
    const uint32_t* whh = g_Whh + (size_t)base * 32;

    // cp.async segment mapping (constant across chunks)
    const int arow = tid >> 3, acol = (tid & 7) * 4;    // +q*32 rows
    const int brow = tid >> 3, bcol = (tid & 7) * 4;    // brow 0..31

    // stage f2 tables (plain loads; visible after first top-of-loop barrier)
#pragma unroll
    for (int q = 0; q < 2; q++) {
        const int idx = (q * 256 + tid) * 4;
        *(float4*)&f2e_s[idx] = *(const float4*)(g_f2e + base + idx);
        *(float4*)&f2s_s[idx] = *(const float4*)(g_f2s + base + idx);
    }

    // prologue: issue chunks 0,1,2
#pragma unroll
    for (int p = 0; p < 3; p++) {
        const uint32_t aslot = smb + AOFF + p * SLOT_A;
        const uint32_t bslot = smb + BOFF + p * SLOT_B;
#pragma unroll
        for (int q = 0; q < 4; q++) {
            const int row = arow + q * 32;
            CP_ASYNC16(aslot + row * 144 + acol * 4,
                       adjb + (size_t)row * N_ + p * CH + acol);
        }
        CP_ASYNC16(bslot + brow * 144 + bcol * 4,
                   whh + (size_t)(p * CH + brow) * 32 + bcol);
        CP_COMMIT();
    }

    const float f1e_lo = g_f1e[base + i0 + r_lo], f1s_lo = g_f1s[base + i0 + r_lo];
    const float f1e_hi = g_f1e[base + i0 + r_hi], f1s_hi = g_f1s[base + i0 + r_hi];
    float dlo = 0.f, dhi = 0.f;

    float c[8][4];
#pragma unroll
    for (int nt = 0; nt < 8; nt++)
#pragma unroll
        for (int q = 0; q < 4; q++) c[nt][q] = 0.f;

    for (int t = 0; t < NCH; t++) {
        CP_WAIT2();          // chunk t's copies complete
        __syncthreads();     // visible to all; also closes WAR on slot (t+3)&3

        // issue chunk t+3 (slot last read in iteration t-1)
        if (t + 3 < NCH) {
            const uint32_t aslot = smb + AOFF + ((t + 3) & 3) * SLOT_A;
            const uint32_t bslot = smb + BOFF + ((t + 3) & 3) * SLOT_B;
#pragma unroll
            for (int q = 0; q < 4; q++) {
                const int row = arow + q * 32;
                CP_ASYNC16(aslot + row * 144 + acol * 4,
                           adjb + (size_t)row * N_ + (t + 3) * CH + acol);
            }
            CP_ASYNC16(bslot + brow * 144 + bcol * 4,
                       whh + (size_t)((t + 3) * CH + brow) * 32 + bcol);
        }
        CP_COMMIT();         // always commit to keep group count aligned

        const char* adjslot = sm + AOFF + (t & 3) * SLOT_A;
        const char* bslot   = sm + BOFF + (t & 3) * SLOT_B;

        // stage1: attention-weight A-fragments (fp32 math, one fp16 rounding)
        uint32_t ah[2][4];
#pragma unroll
        for (int s = 0; s < 2; s++) {
            const int co = s * 64 + tg * 8;          // (s*16 + 2tg) * 4 bytes
            const int2 alo0 = *(const int2*)(adjslot + r_lo * 144 + co);
            const int2 alo8 = *(const int2*)(adjslot + r_lo * 144 + co + 32);
            const int2 ahi0 = *(const int2*)(adjslot + r_hi * 144 + co);
            const int2 ahi8 = *(const int2*)(adjslot + r_hi * 144 + co + 32);

            const int jb = t * CH + s * 16 + 2 * tg;
            const float2 e01 = *(const float2*)&f2e_s[jb];
            const float2 e89 = *(const float2*)&f2e_s[jb + 8];
            const float2 s01 = *(const float2*)&f2s_s[jb];
            const float2 s89 = *(const float2*)&f2s_s[jb + 8];

            float wl0 = (alo0.x > 0) ? ex2(fmaxf(f1e_lo + e01.x, f1s_lo + s01.x)) : 0.f;
            float wl1 = (alo0.y > 0) ? ex2(fmaxf(f1e_lo + e01.y, f1s_lo + s01.y)) : 0.f;
            float wl8 = (alo8.x > 0) ? ex2(fmaxf(f1e_lo + e89.x, f1s_lo + s89.x)) : 0.f;
            float wl9 = (alo8.y > 0) ? ex2(fmaxf(f1e_lo + e89.y, f1s_lo + s89.y)) : 0.f;
            float wh0 = (ahi0.x > 0) ? ex2(fmaxf(f1e_hi + e01.x, f1s_hi + s01.x)) : 0.f;
            float wh1 = (ahi0.y > 0) ? ex2(fmaxf(f1e_hi + e01.y, f1s_hi + s01.y)) : 0.f;
            float wh8 = (ahi8.x > 0) ? ex2(fmaxf(f1e_hi + e89.x, f1s_hi + s89.x)) : 0.f;
            float wh9 = (ahi8.y > 0) ? ex2(fmaxf(f1e_hi + e89.y, f1s_hi + s89.y)) : 0.f;

            dlo += (wl0 + wl1) + (wl8 + wl9);
            dhi += (wh0 + wh1) + (wh8 + wh9);

            ah[s][0] = pack2h(wl0, wl1);
            ah[s][1] = pack2h(wh0, wh1);
            ah[s][2] = pack2h(wl8, wl9);
            ah[s][3] = pack2h(wh8, wh9);
        }

        // ldmatrix B fragments + 16 mma per chunk
#pragma unroll
        for (int s = 0; s < 2; s++) {
            const int kr = s * 16 + (lane & 15);
            const int nc = ((lane >> 4) << 3);
#pragma unroll
            for (int n16 = 0; n16 < 4; n16++) {
                uint32_t b0, b1, b2, b3;
                ldsm4t(b0, b1, b2, b3, bslot + kr * 144 + (n16 * 16 + nc) * 2);
                mma16816(c[n16 * 2],     ah[s], b0, b1);
                mma16816(c[n16 * 2 + 1], ah[s], b2, b3);
            }
        }
    }

    // ---- softmax denominators (reduce over the 4 lanes sharing a row) ----
    dlo += __shfl_xor_sync(0xffffffffu, dlo, 1);
    dlo += __shfl_xor_sync(0xffffffffu, dlo, 2);
    dhi += __shfl_xor_sync(0xffffffffu, dhi, 1);
    dhi += __shfl_xor_sync(0xffffffffu, dhi, 2);
    const float rlo = __fdividef(1.f, dlo);
    const float rhi = __fdividef(1.f, dhi);

    float* olo = out + (size_t)(base + i0 + r_lo) * HID;
    float* ohi = out + (size_t)(base + i0 + r_hi) * HID;
#pragma unroll
    for (int nt = 0; nt < 8; nt++) {
        *(float2*)&olo[nt * 8 + 2 * tg] = make_float2(c[nt][0] * rlo, c[nt][1] * rlo);
        *(float2*)&ohi[nt * 8 + 2 * tg] = make_float2(c[nt][2] * rhi, c[nt][3] * rhi);
    }
}

// ---------------------------------------------------------------------------
extern "C" void kernel_launch(void* const* d_in, const int* in_sizes, int n_in,
                              void* d_out, int out_size) {
    const float* X  = (const float*)d_in[0];   // node_features [8,2048,256]
    const int*   A  = (const int*)d_in[1];     // adj [8,2048,2048]
    const float* W  = (const float*)d_in[2];   // W [256,64]
    const float* av = (const float*)d_in[3];   // a [128,1]
    float* out = (float*)d_out;                // [8,2048,64] f32

    cudaFuncSetAttribute(gat_main, cudaFuncAttributeMaxDynamicSharedMemorySize,
                         SMEM_DYN);

    gemm_wh<<<(B_ * N_) / 64, 256>>>(X, W, av);
    gat_main<<<dim3(B_ * (N_ / TI)), 256, SMEM_DYN>>>(A, out);
}